// round 1
// baseline (speedup 1.0000x reference)
#include <cuda_runtime.h>
#include <math.h>

// Problem constants
#define BB      32      // batch
#define HH      32      // q heads
#define KVHN    8       // kv heads
#define DD      128     // head dim
#define SS      2048    // seq len
#define BLKSZ   16      // paged block size
#define NCHUNK  32      // split-KV chunks per batch
#define CS      64      // positions per chunk (SS / NCHUNK)
#define NT      256     // threads per CTA (8 warps, one per kv head)
#define SCALE   0.08838834764831845f   // 1/sqrt(128)

// Scratch for split-KV partials (device globals: no allocation)
__device__ float g_acc[(size_t)BB * NCHUNK * HH * DD];  // 16 MB
__device__ float g_m[BB * NCHUNK * HH];
__device__ float g_l[BB * NCHUNK * HH];

// fp32 Cody-Waite reduction of angle into [-pi, pi], then accurate sincos.
// Robust even under -use_fast_math (reduced arg is in the accurate range).
__device__ __forceinline__ void rope_sincos(float ang, float* s, float* c) {
    const float INV2PI = 0.15915494309189535f;
    const float C1 = 6.28125f;                 // exact in fp32 (8 mantissa bits)
    const float C2 = 0.0019353071795864769f;   // 2*pi - C1
    float n = rintf(ang * INV2PI);
    float r = fmaf(-n, C1, ang);
    r = fmaf(-n, C2, r);
    sincosf(r, s, c);
}

__global__ __launch_bounds__(NT, 2) void attn_partial(
    const float* __restrict__ q,
    const float* __restrict__ kc,
    const float* __restrict__ vc,
    const int*   __restrict__ slot_map,
    const int*   __restrict__ pos)
{
    __shared__ float  invf_sm[64];           // inv_freq per rope pair
    __shared__ float2 cs_tab[CS * 64];       // [s][pair] = (cos, sin)
    __shared__ float4 sc_sm[KVHN * CS];      // [warp][s] = 4 head scores
    __shared__ int    slot_sm[CS];

    const int b     = blockIdx.y;
    const int chunk = blockIdx.x;
    const int s0    = chunk * CS;
    const int tid   = threadIdx.x;
    const int w     = tid >> 5;              // warp = kv head
    const int l     = tid & 31;

    // inv_freq[i] = 10000^(-i/64) computed as expf(-(i/64)*ln(10000)),
    // matching XLA's pow lowering in fp32.
    if (tid < 64) {
        float fi = (float)tid * 0.015625f;   // i/64, exact
        invf_sm[tid] = expf(-fi * 9.210340371976184f);
    }
    if (tid < CS) slot_sm[tid] = slot_map[b * SS + s0 + tid];
    __syncthreads();

    // Build rope cos/sin table for this (b, chunk): shared across all 8 kv heads.
    for (int idx = tid; idx < CS * 64; idx += NT) {
        int s = idx >> 6;
        int i = idx & 63;
        float p   = (float)pos[b * SS + s0 + s];
        float ang = p * invf_sm[i];          // fp32, matches reference
        float sv, cv;
        rope_sincos(ang, &sv, &cv);
        cs_tab[idx] = make_float2(cv, sv);
    }

    // Load + rope q for this warp's 4 heads, folding in SCALE.
    // Lane l owns rope pairs i=2l and i=2l+1: dims {2l,2l+1} and {2l+64,2l+65}.
    float2 qlo[4], qhi[4];
    {
        float pq = (float)pos[b * SS + SS - 1];
        float a0 = pq * invf_sm[2 * l];
        float a1 = pq * invf_sm[2 * l + 1];
        float s0v, c0v, s1v, c1v;
        rope_sincos(a0, &s0v, &c0v);
        rope_sincos(a1, &s1v, &c1v);
        #pragma unroll
        for (int j = 0; j < 4; j++) {
            const float* qp = q + ((size_t)(b * HH + w * 4 + j)) * DD;
            float2 alo = *(const float2*)(qp + 2 * l);
            float2 ahi = *(const float2*)(qp + 64 + 2 * l);
            qlo[j].x = SCALE * (alo.x * c0v - ahi.x * s0v);
            qhi[j].x = SCALE * (ahi.x * c0v + alo.x * s0v);
            qlo[j].y = SCALE * (alo.y * c1v - ahi.y * s1v);
            qhi[j].y = SCALE * (ahi.y * c1v + alo.y * s1v);
        }
    }
    __syncthreads();

    // ---- Phase K: scores for all CS positions (4 heads per warp) ----
    float m0 = -1e30f, m1 = -1e30f, m2 = -1e30f, m3 = -1e30f;
    #pragma unroll 4
    for (int s = 0; s < CS; s++) {
        int slot = slot_sm[s];
        float2 klo = make_float2(0.f, 0.f), khi = make_float2(0.f, 0.f);
        if (slot >= 0) {
            const float* kp = kc + ((size_t)(slot >> 4) * (BLKSZ * KVHN * DD)
                                    + (size_t)(slot & 15) * (KVHN * DD)
                                    + w * DD);
            klo = *(const float2*)(kp + 2 * l);
            khi = *(const float2*)(kp + 64 + 2 * l);
        }
        // cos/sin for pairs 2l and 2l+1 in one 16B shared load
        float4 cs4 = *(const float4*)&cs_tab[s * 64 + 2 * l];
        float rlx = klo.x * cs4.x - khi.x * cs4.y;
        float rhx = khi.x * cs4.x + klo.x * cs4.y;
        float rly = klo.y * cs4.z - khi.y * cs4.w;
        float rhy = khi.y * cs4.z + klo.y * cs4.w;

        float p0 = qlo[0].x * rlx + qlo[0].y * rly + qhi[0].x * rhx + qhi[0].y * rhy;
        float p1 = qlo[1].x * rlx + qlo[1].y * rly + qhi[1].x * rhx + qhi[1].y * rhy;
        float p2 = qlo[2].x * rlx + qlo[2].y * rly + qhi[2].x * rhx + qhi[2].y * rhy;
        float p3 = qlo[3].x * rlx + qlo[3].y * rly + qhi[3].x * rhx + qhi[3].y * rhy;

        #pragma unroll
        for (int off = 16; off > 0; off >>= 1) {
            p0 += __shfl_xor_sync(0xffffffffu, p0, off);
            p1 += __shfl_xor_sync(0xffffffffu, p1, off);
            p2 += __shfl_xor_sync(0xffffffffu, p2, off);
            p3 += __shfl_xor_sync(0xffffffffu, p3, off);
        }
        m0 = fmaxf(m0, p0); m1 = fmaxf(m1, p1);
        m2 = fmaxf(m2, p2); m3 = fmaxf(m3, p3);
        if (l == 0) sc_sm[w * CS + s] = make_float4(p0, p1, p2, p3);
    }
    __syncwarp();

    // ---- Phase V: single exp per score (chunk max known), accumulate V ----
    float acc[16];
    #pragma unroll
    for (int i = 0; i < 16; i++) acc[i] = 0.f;
    float l0 = 0.f, l1 = 0.f, l2 = 0.f, l3 = 0.f;

    #pragma unroll 4
    for (int s = 0; s < CS; s++) {
        float4 sc = sc_sm[w * CS + s];
        float e0 = __expf(sc.x - m0);
        float e1 = __expf(sc.y - m1);
        float e2 = __expf(sc.z - m2);
        float e3 = __expf(sc.w - m3);
        l0 += e0; l1 += e1; l2 += e2; l3 += e3;

        int slot = slot_sm[s];
        float2 vlo = make_float2(0.f, 0.f), vhi = make_float2(0.f, 0.f);
        if (slot >= 0) {
            const float* vp = vc + ((size_t)(slot >> 4) * (BLKSZ * KVHN * DD)
                                    + (size_t)(slot & 15) * (KVHN * DD)
                                    + w * DD);
            vlo = *(const float2*)(vp + 2 * l);
            vhi = *(const float2*)(vp + 64 + 2 * l);
        }
        acc[0]  += e0 * vlo.x; acc[1]  += e0 * vlo.y; acc[2]  += e0 * vhi.x; acc[3]  += e0 * vhi.y;
        acc[4]  += e1 * vlo.x; acc[5]  += e1 * vlo.y; acc[6]  += e1 * vhi.x; acc[7]  += e1 * vhi.y;
        acc[8]  += e2 * vlo.x; acc[9]  += e2 * vlo.y; acc[10] += e2 * vhi.x; acc[11] += e2 * vhi.y;
        acc[12] += e3 * vlo.x; acc[13] += e3 * vlo.y; acc[14] += e3 * vhi.x; acc[15] += e3 * vhi.y;
    }

    // ---- Write partials ----
    #pragma unroll
    for (int j = 0; j < 4; j++) {
        int h = w * 4 + j;
        size_t base = (((size_t)b * NCHUNK + chunk) * HH + h) * DD;
        *(float2*)(g_acc + base + 2 * l)      = make_float2(acc[j * 4 + 0], acc[j * 4 + 1]);
        *(float2*)(g_acc + base + 64 + 2 * l) = make_float2(acc[j * 4 + 2], acc[j * 4 + 3]);
    }
    if (l == 0) {
        int mb = (b * NCHUNK + chunk) * HH + w * 4;
        g_m[mb + 0] = m0; g_m[mb + 1] = m1; g_m[mb + 2] = m2; g_m[mb + 3] = m3;
        g_l[mb + 0] = l0; g_l[mb + 1] = l1; g_l[mb + 2] = l2; g_l[mb + 3] = l3;
    }
}

// Merge split-KV partials: out[b,h,d] = sum_c e^{m_c-M} acc_c[d] / sum_c e^{m_c-M} l_c
__global__ void attn_combine(float* __restrict__ out)
{
    int bh = blockIdx.x;          // b*H + h
    int b  = bh >> 5;
    int h  = bh & 31;
    int d  = threadIdx.x;         // 0..127

    float M = -1e30f;
    #pragma unroll
    for (int c = 0; c < NCHUNK; c++)
        M = fmaxf(M, g_m[(b * NCHUNK + c) * HH + h]);

    float L = 0.f, o = 0.f;
    #pragma unroll
    for (int c = 0; c < NCHUNK; c++) {
        int idx  = (b * NCHUNK + c) * HH + h;
        float al = __expf(g_m[idx] - M);
        L += al * g_l[idx];
        o += al * g_acc[(size_t)idx * DD + d];
    }
    out[(size_t)bh * DD + d] = o / L;
}

extern "C" void kernel_launch(void* const* d_in, const int* in_sizes, int n_in,
                              void* d_out, int out_size) {
    const float* query   = (const float*)d_in[0];
    const float* k_cache = (const float*)d_in[1];
    const float* v_cache = (const float*)d_in[2];
    const int*   slots   = (const int*)d_in[3];
    const int*   pos     = (const int*)d_in[4];
    float*       out     = (float*)d_out;

    attn_partial<<<dim3(NCHUNK, BB), NT>>>(query, k_cache, v_cache, slots, pos);
    attn_combine<<<BB * HH, DD>>>(out);
}

// round 2
// speedup vs baseline: 1.3325x; 1.3325x over previous
#include <cuda_runtime.h>
#include <math.h>

#define BB      32
#define HH      32
#define KVHN    8
#define DD      128
#define SS      2048
#define NCHUNK  32
#define CS      64            // positions per chunk
#define NT      256           // 8 warps = 8 kv heads
#define SCALE   0.08838834764831845f
#define ROWF    (KVHN*DD)     // floats per slot row (1024)

__device__ float g_acc[(size_t)BB * NCHUNK * HH * DD];  // 16 MB
__device__ float g_m[BB * NCHUNK * HH];
__device__ float g_l[BB * NCHUNK * HH];

// fp32 Cody-Waite reduction into [-pi,pi] then accurate sincos
__device__ __forceinline__ void rope_sincos(float ang, float* s, float* c) {
    const float INV2PI = 0.15915494309189535f;
    const float C1 = 6.28125f;
    const float C2 = 0.0019353071795864769f;
    float n = rintf(ang * INV2PI);
    float r = fmaf(-n, C1, ang);
    r = fmaf(-n, C2, r);
    sincosf(r, s, c);
}

__global__ __launch_bounds__(NT, 2) void attn_partial(
    const float* __restrict__ q,
    const float* __restrict__ kc,
    const float* __restrict__ vc,
    const int*   __restrict__ slot_map,
    const int*   __restrict__ pos)
{
    __shared__ float  cos_tab[CS * 64];    // 16 KB
    __shared__ float  sin_tab[CS * 64];    // 16 KB
    __shared__ float4 sc_sm[KVHN * CS];    // 8 KB  scores -> exp weights
    __shared__ int    slot_sm[CS];
    __shared__ float  invf_sm[64];

    const int b     = blockIdx.y;
    const int chunk = blockIdx.x;
    const int s0    = chunk * CS;
    const int tid   = threadIdx.x;
    const int w     = tid >> 5;            // warp = kv head
    const int l     = tid & 31;
    const int c     = l & 15;              // float4 chunk within row (K phase)
    const int r     = l >> 4;              // row parity within pair

    if (tid < 64) {
        float fi = (float)tid * 0.015625f;
        invf_sm[tid] = expf(-fi * 9.210340371976184f);
    }
    if (tid < CS) slot_sm[tid] = slot_map[b * SS + s0 + tid];
    __syncthreads();

    // cos/sin tables for this (b,chunk), shared by all 8 kv heads
    for (int idx = tid; idx < CS * 64; idx += NT) {
        int s = idx >> 6;
        int i = idx & 63;
        float p = (float)pos[b * SS + s0 + s];
        float sv, cv;
        rope_sincos(p * invf_sm[i], &sv, &cv);
        cos_tab[idx] = cv;
        sin_tab[idx] = sv;
    }

    // Rope q (4 heads per warp) for this lane's dims {4c..4c+3, +64}; fold SCALE.
    float4 ql[4], qh[4];
    {
        float pq = (float)pos[b * SS + SS - 1];
        float cq[4], sq[4];
        #pragma unroll
        for (int i = 0; i < 4; i++)
            rope_sincos(pq * invf_sm[4 * c + i], &sq[i], &cq[i]);
        #pragma unroll
        for (int j = 0; j < 4; j++) {
            const float4* qp = (const float4*)(q + ((size_t)(b * HH + w * 4 + j)) * DD);
            float4 alo = qp[c];
            float4 ahi = qp[c + 16];
            ql[j].x = SCALE * (alo.x * cq[0] - ahi.x * sq[0]);
            qh[j].x = SCALE * (ahi.x * cq[0] + alo.x * sq[0]);
            ql[j].y = SCALE * (alo.y * cq[1] - ahi.y * sq[1]);
            qh[j].y = SCALE * (ahi.y * cq[1] + alo.y * sq[1]);
            ql[j].z = SCALE * (alo.z * cq[2] - ahi.z * sq[2]);
            qh[j].z = SCALE * (ahi.z * cq[2] + alo.z * sq[2]);
            ql[j].w = SCALE * (alo.w * cq[3] - ahi.w * sq[3]);
            qh[j].w = SCALE * (ahi.w * cq[3] + alo.w * sq[3]);
        }
    }
    __syncthreads();

    // ---- K phase: 2 rows per iteration (half-warp each). ----
    float m0 = -1e30f, m1 = -1e30f, m2 = -1e30f, m3 = -1e30f;
    #pragma unroll 4
    for (int sp = 0; sp < CS; sp += 2) {
        const int s = sp + r;
        const int slot = slot_sm[s];
        float4 klo = make_float4(0.f, 0.f, 0.f, 0.f);
        float4 khi = make_float4(0.f, 0.f, 0.f, 0.f);
        if (slot >= 0) {
            const float* kp = kc + (size_t)slot * ROWF + w * DD + 4 * c;
            klo = *(const float4*)kp;
            khi = *(const float4*)(kp + 64);
        }
        const float4 co = *(const float4*)&cos_tab[s * 64 + 4 * c];
        const float4 si = *(const float4*)&sin_tab[s * 64 + 4 * c];

        float rlx = klo.x * co.x - khi.x * si.x, rhx = khi.x * co.x + klo.x * si.x;
        float rly = klo.y * co.y - khi.y * si.y, rhy = khi.y * co.y + klo.y * si.y;
        float rlz = klo.z * co.z - khi.z * si.z, rhz = khi.z * co.z + klo.z * si.z;
        float rlw = klo.w * co.w - khi.w * si.w, rhw = khi.w * co.w + klo.w * si.w;

        float p0 = ql[0].x * rlx + ql[0].y * rly + ql[0].z * rlz + ql[0].w * rlw
                 + qh[0].x * rhx + qh[0].y * rhy + qh[0].z * rhz + qh[0].w * rhw;
        float p1 = ql[1].x * rlx + ql[1].y * rly + ql[1].z * rlz + ql[1].w * rlw
                 + qh[1].x * rhx + qh[1].y * rhy + qh[1].z * rhz + qh[1].w * rhw;
        float p2 = ql[2].x * rlx + ql[2].y * rly + ql[2].z * rlz + ql[2].w * rlw
                 + qh[2].x * rhx + qh[2].y * rhy + qh[2].z * rhz + qh[2].w * rhw;
        float p3 = ql[3].x * rlx + ql[3].y * rly + ql[3].z * rlz + ql[3].w * rlw
                 + qh[3].x * rhx + qh[3].y * rhy + qh[3].z * rhz + qh[3].w * rhw;

        // Reduce over 16 lanes (within each half-warp): 4 stages
        #pragma unroll
        for (int off = 1; off <= 8; off <<= 1) {
            p0 += __shfl_xor_sync(0xffffffffu, p0, off);
            p1 += __shfl_xor_sync(0xffffffffu, p1, off);
            p2 += __shfl_xor_sync(0xffffffffu, p2, off);
            p3 += __shfl_xor_sync(0xffffffffu, p3, off);
        }
        m0 = fmaxf(m0, p0); m1 = fmaxf(m1, p1);
        m2 = fmaxf(m2, p2); m3 = fmaxf(m3, p3);
        if (c == 0) sc_sm[w * CS + s] = make_float4(p0, p1, p2, p3);  // lanes 0,16
    }
    // merge the two half-warp maxima
    m0 = fmaxf(m0, __shfl_xor_sync(0xffffffffu, m0, 16));
    m1 = fmaxf(m1, __shfl_xor_sync(0xffffffffu, m1, 16));
    m2 = fmaxf(m2, __shfl_xor_sync(0xffffffffu, m2, 16));
    m3 = fmaxf(m3, __shfl_xor_sync(0xffffffffu, m3, 16));
    __syncwarp();

    // ---- Convert scores -> exp weights in shared (4 MUFU per lane total) ----
    {
        float4 sca = sc_sm[w * CS + l];
        sca.x = __expf(sca.x - m0); sca.y = __expf(sca.y - m1);
        sca.z = __expf(sca.z - m2); sca.w = __expf(sca.w - m3);
        sc_sm[w * CS + l] = sca;
        float4 scb = sc_sm[w * CS + 32 + l];
        scb.x = __expf(scb.x - m0); scb.y = __expf(scb.y - m1);
        scb.z = __expf(scb.z - m2); scb.w = __expf(scb.w - m3);
        sc_sm[w * CS + 32 + l] = scb;
    }
    __syncwarp();

    // ---- V phase: lane owns dims 4l..4l+3, one row per iteration ----
    float4 a0 = make_float4(0,0,0,0), a1 = a0, a2 = a0, a3 = a0;
    float l0 = 0.f, l1 = 0.f, l2 = 0.f, l3 = 0.f;
    #pragma unroll 4
    for (int s = 0; s < CS; s++) {
        const float4 e = sc_sm[w * CS + s];     // broadcast
        l0 += e.x; l1 += e.y; l2 += e.z; l3 += e.w;
        const int slot = slot_sm[s];
        float4 v4 = make_float4(0.f, 0.f, 0.f, 0.f);
        if (slot >= 0)
            v4 = *(const float4*)(vc + (size_t)slot * ROWF + w * DD + 4 * l);
        a0.x += e.x * v4.x; a0.y += e.x * v4.y; a0.z += e.x * v4.z; a0.w += e.x * v4.w;
        a1.x += e.y * v4.x; a1.y += e.y * v4.y; a1.z += e.y * v4.z; a1.w += e.y * v4.w;
        a2.x += e.z * v4.x; a2.y += e.z * v4.y; a2.z += e.z * v4.z; a2.w += e.z * v4.w;
        a3.x += e.w * v4.x; a3.y += e.w * v4.y; a3.z += e.w * v4.z; a3.w += e.w * v4.w;
    }

    // ---- Write partials (float4, coalesced) ----
    {
        size_t base = (((size_t)b * NCHUNK + chunk) * HH + w * 4) * DD;
        float4* ga = (float4*)g_acc;
        ga[(base >> 2) + l]                = a0;
        ga[((base + DD) >> 2) + l]         = a1;
        ga[((base + 2 * DD) >> 2) + l]     = a2;
        ga[((base + 3 * DD) >> 2) + l]     = a3;
    }
    if (l == 0) {
        int mb = (b * NCHUNK + chunk) * HH + w * 4;
        g_m[mb + 0] = m0; g_m[mb + 1] = m1; g_m[mb + 2] = m2; g_m[mb + 3] = m3;
        g_l[mb + 0] = l0; g_l[mb + 1] = l1; g_l[mb + 2] = l2; g_l[mb + 3] = l3;
    }
}

// Merge split-KV partials: warp per (b,h), float4 per lane.
__global__ __launch_bounds__(128) void attn_combine(float* __restrict__ out)
{
    const int wid = threadIdx.x >> 5;
    const int l   = threadIdx.x & 31;
    const int bh  = blockIdx.x * 4 + wid;
    const int b   = bh >> 5;
    const int h   = bh & 31;

    float M = -1e30f;
    #pragma unroll
    for (int cn = 0; cn < NCHUNK; cn++)
        M = fmaxf(M, g_m[(b * NCHUNK + cn) * HH + h]);

    float L = 0.f;
    float4 o = make_float4(0.f, 0.f, 0.f, 0.f);
    #pragma unroll 4
    for (int cn = 0; cn < NCHUNK; cn++) {
        int idx = (b * NCHUNK + cn) * HH + h;
        float al = __expf(g_m[idx] - M);
        L += al * g_l[idx];
        float4 a = ((const float4*)g_acc)[(((size_t)idx * DD) >> 2) + l];
        o.x += al * a.x; o.y += al * a.y; o.z += al * a.z; o.w += al * a.w;
    }
    float inv = 1.0f / L;
    o.x *= inv; o.y *= inv; o.z *= inv; o.w *= inv;
    ((float4*)out)[(size_t)bh * 32 + l] = o;
}

extern "C" void kernel_launch(void* const* d_in, const int* in_sizes, int n_in,
                              void* d_out, int out_size) {
    const float* query   = (const float*)d_in[0];
    const float* k_cache = (const float*)d_in[1];
    const float* v_cache = (const float*)d_in[2];
    const int*   slots   = (const int*)d_in[3];
    const int*   pos     = (const int*)d_in[4];
    float*       out     = (float*)d_out;

    attn_partial<<<dim3(NCHUNK, BB), NT>>>(query, k_cache, v_cache, slots, pos);
    attn_combine<<<BB * HH / 4, 128>>>(out);
}

// round 3
// speedup vs baseline: 1.9341x; 1.4515x over previous
#include <cuda_runtime.h>
#include <math.h>

#define BB      32
#define HH      32
#define KVHN    8
#define DD      128
#define SS      2048
#define NCHUNK  32
#define CS      64            // positions per chunk
#define HCS     32            // positions per table pass
#define NT      256           // 8 warps = 8 kv heads
#define SCALE   0.08838834764831845f
#define ROWF    (KVHN*DD)     // floats per slot row (1024)

__device__ float g_acc[(size_t)BB * NCHUNK * HH * DD];  // 16 MB
__device__ float g_m[BB * NCHUNK * HH];
__device__ float g_l[BB * NCHUNK * HH];

// fp32 Cody-Waite reduction into [-pi,pi] then accurate sincos
__device__ __forceinline__ void rope_sincos(float ang, float* s, float* c) {
    const float INV2PI = 0.15915494309189535f;
    const float C1 = 6.28125f;
    const float C2 = 0.0019353071795864769f;
    float n = rintf(ang * INV2PI);
    float r = fmaf(-n, C1, ang);
    r = fmaf(-n, C2, r);
    sincosf(r, s, c);
}

__global__ __launch_bounds__(NT, 4) void attn_partial(
    const float* __restrict__ q,
    const float* __restrict__ kc,
    const float* __restrict__ vc,
    const int*   __restrict__ slot_map,
    const int*   __restrict__ pos)
{
    __shared__ float  cos_tab[HCS * 64];          // 8 KB (per pass)
    __shared__ float  sin_tab[HCS * 64];          // 8 KB
    __shared__ float4 q_sm[KVHN * 4 * 2 * 16];    // 16 KB  [w][head j][lo/hi][c]
    __shared__ float4 sc_sm[KVHN * CS];           // 8 KB   scores -> exp weights
    __shared__ int    slot_sm[CS];
    __shared__ float  pos_sm[CS];
    __shared__ float  invf_sm[64];

    const int b     = blockIdx.y;
    const int chunk = blockIdx.x;
    const int s0    = chunk * CS;
    const int tid   = threadIdx.x;
    const int w     = tid >> 5;            // warp = kv head
    const int l     = tid & 31;
    const int c     = l & 15;              // float4 chunk within row (K phase)
    const int r     = l >> 4;              // row parity within pair

    if (tid < 64) {
        float fi = (float)tid * 0.015625f;
        invf_sm[tid] = expf(-fi * 9.210340371976184f);
    }
    if (tid < CS) {
        slot_sm[tid] = slot_map[b * SS + s0 + tid];
        pos_sm[tid]  = (float)pos[b * SS + s0 + tid];
    }
    __syncthreads();

    // Rope q (4 heads per warp) for dims {4c..4c+3, +64}; fold SCALE; store to shared.
    if (r == 0) {
        float pq = (float)pos[b * SS + SS - 1];
        float cq[4], sq[4];
        #pragma unroll
        for (int i = 0; i < 4; i++)
            rope_sincos(pq * invf_sm[4 * c + i], &sq[i], &cq[i]);
        #pragma unroll
        for (int j = 0; j < 4; j++) {
            const float4* qp = (const float4*)(q + ((size_t)(b * HH + w * 4 + j)) * DD);
            float4 alo = qp[c];
            float4 ahi = qp[c + 16];
            float4 ql, qh;
            ql.x = SCALE * (alo.x * cq[0] - ahi.x * sq[0]);
            qh.x = SCALE * (ahi.x * cq[0] + alo.x * sq[0]);
            ql.y = SCALE * (alo.y * cq[1] - ahi.y * sq[1]);
            qh.y = SCALE * (ahi.y * cq[1] + alo.y * sq[1]);
            ql.z = SCALE * (alo.z * cq[2] - ahi.z * sq[2]);
            qh.z = SCALE * (ahi.z * cq[2] + alo.z * sq[2]);
            ql.w = SCALE * (alo.w * cq[3] - ahi.w * sq[3]);
            qh.w = SCALE * (ahi.w * cq[3] + alo.w * sq[3]);
            q_sm[((w * 4 + j) * 2 + 0) * 16 + c] = ql;
            q_sm[((w * 4 + j) * 2 + 1) * 16 + c] = qh;
        }
    }

    // ---- K phase in two passes of HCS positions (table rebuilt between) ----
    float m0 = -1e30f, m1 = -1e30f, m2 = -1e30f, m3 = -1e30f;

    #pragma unroll
    for (int pass = 0; pass < 2; pass++) {
        // build cos/sin for positions [pass*HCS, pass*HCS+HCS)
        for (int idx = tid; idx < HCS * 64; idx += NT) {
            int s = idx >> 6;
            int i = idx & 63;
            float sv, cv;
            rope_sincos(pos_sm[pass * HCS + s] * invf_sm[i], &sv, &cv);
            cos_tab[idx] = cv;
            sin_tab[idx] = sv;
        }
        __syncthreads();

        #pragma unroll 4
        for (int sp = 0; sp < HCS; sp += 2) {
            const int sl = sp + r;                 // table-local position
            const int s  = pass * HCS + sl;        // chunk-local position
            const int slot = slot_sm[s];
            float4 klo = make_float4(0.f, 0.f, 0.f, 0.f);
            float4 khi = make_float4(0.f, 0.f, 0.f, 0.f);
            if (slot >= 0) {
                const float* kp = kc + (size_t)slot * ROWF + w * DD + 4 * c;
                klo = *(const float4*)kp;
                khi = *(const float4*)(kp + 64);
            }
            const float4 co = *(const float4*)&cos_tab[sl * 64 + 4 * c];
            const float4 si = *(const float4*)&sin_tab[sl * 64 + 4 * c];

            float rlx = klo.x * co.x - khi.x * si.x, rhx = khi.x * co.x + klo.x * si.x;
            float rly = klo.y * co.y - khi.y * si.y, rhy = khi.y * co.y + klo.y * si.y;
            float rlz = klo.z * co.z - khi.z * si.z, rhz = khi.z * co.z + klo.z * si.z;
            float rlw = klo.w * co.w - khi.w * si.w, rhw = khi.w * co.w + klo.w * si.w;

            float p[4];
            #pragma unroll
            for (int j = 0; j < 4; j++) {
                float4 ql = q_sm[((w * 4 + j) * 2 + 0) * 16 + c];
                float4 qh = q_sm[((w * 4 + j) * 2 + 1) * 16 + c];
                p[j] = ql.x * rlx + ql.y * rly + ql.z * rlz + ql.w * rlw
                     + qh.x * rhx + qh.y * rhy + qh.z * rhz + qh.w * rhw;
            }
            #pragma unroll
            for (int off = 1; off <= 8; off <<= 1) {
                p[0] += __shfl_xor_sync(0xffffffffu, p[0], off);
                p[1] += __shfl_xor_sync(0xffffffffu, p[1], off);
                p[2] += __shfl_xor_sync(0xffffffffu, p[2], off);
                p[3] += __shfl_xor_sync(0xffffffffu, p[3], off);
            }
            m0 = fmaxf(m0, p[0]); m1 = fmaxf(m1, p[1]);
            m2 = fmaxf(m2, p[2]); m3 = fmaxf(m3, p[3]);
            if (c == 0) sc_sm[w * CS + s] = make_float4(p[0], p[1], p[2], p[3]);
        }
        __syncthreads();   // protect table before rebuild / before V phase reuse
    }

    // merge the two half-warp maxima
    m0 = fmaxf(m0, __shfl_xor_sync(0xffffffffu, m0, 16));
    m1 = fmaxf(m1, __shfl_xor_sync(0xffffffffu, m1, 16));
    m2 = fmaxf(m2, __shfl_xor_sync(0xffffffffu, m2, 16));
    m3 = fmaxf(m3, __shfl_xor_sync(0xffffffffu, m3, 16));

    // ---- scores -> exp weights in shared (4 MUFU per lane total) ----
    {
        float4 sca = sc_sm[w * CS + l];
        sca.x = __expf(sca.x - m0); sca.y = __expf(sca.y - m1);
        sca.z = __expf(sca.z - m2); sca.w = __expf(sca.w - m3);
        sc_sm[w * CS + l] = sca;
        float4 scb = sc_sm[w * CS + 32 + l];
        scb.x = __expf(scb.x - m0); scb.y = __expf(scb.y - m1);
        scb.z = __expf(scb.z - m2); scb.w = __expf(scb.w - m3);
        sc_sm[w * CS + 32 + l] = scb;
    }
    __syncwarp();

    // ---- V phase: lane owns dims 4l..4l+3, one row per iteration ----
    float4 a0 = make_float4(0,0,0,0), a1 = a0, a2 = a0, a3 = a0;
    float l0 = 0.f, l1 = 0.f, l2 = 0.f, l3 = 0.f;
    #pragma unroll 4
    for (int s = 0; s < CS; s++) {
        const float4 e = sc_sm[w * CS + s];     // broadcast
        l0 += e.x; l1 += e.y; l2 += e.z; l3 += e.w;
        const int slot = slot_sm[s];
        float4 v4 = make_float4(0.f, 0.f, 0.f, 0.f);
        if (slot >= 0)
            v4 = *(const float4*)(vc + (size_t)slot * ROWF + w * DD + 4 * l);
        a0.x += e.x * v4.x; a0.y += e.x * v4.y; a0.z += e.x * v4.z; a0.w += e.x * v4.w;
        a1.x += e.y * v4.x; a1.y += e.y * v4.y; a1.z += e.y * v4.z; a1.w += e.y * v4.w;
        a2.x += e.z * v4.x; a2.y += e.z * v4.y; a2.z += e.z * v4.z; a2.w += e.z * v4.w;
        a3.x += e.w * v4.x; a3.y += e.w * v4.y; a3.z += e.w * v4.z; a3.w += e.w * v4.w;
    }

    // ---- Write partials (float4, coalesced) ----
    {
        size_t base = (((size_t)b * NCHUNK + chunk) * HH + w * 4) * DD;
        float4* ga = (float4*)g_acc;
        ga[(base >> 2) + l]            = a0;
        ga[((base + DD) >> 2) + l]     = a1;
        ga[((base + 2 * DD) >> 2) + l] = a2;
        ga[((base + 3 * DD) >> 2) + l] = a3;
    }
    if (l == 0) {
        int mb = (b * NCHUNK + chunk) * HH + w * 4;
        g_m[mb + 0] = m0; g_m[mb + 1] = m1; g_m[mb + 2] = m2; g_m[mb + 3] = m3;
        g_l[mb + 0] = l0; g_l[mb + 1] = l1; g_l[mb + 2] = l2; g_l[mb + 3] = l3;
    }
}

// Combine: one block per (b,h); 4 warps x 8 chunks each; merge via shared.
__global__ __launch_bounds__(128) void attn_combine(float* __restrict__ out)
{
    __shared__ float4 osm[4][32];
    __shared__ float  Lsm[4];

    const int bh = blockIdx.x;
    const int b  = bh >> 5;
    const int h  = bh & 31;
    const int wj = threadIdx.x >> 5;
    const int l  = threadIdx.x & 31;

    // lane l holds m of chunk l; butterfly max -> global M in every lane
    float mraw = g_m[(b * NCHUNK + l) * HH + h];
    float M = mraw;
    #pragma unroll
    for (int off = 16; off > 0; off >>= 1)
        M = fmaxf(M, __shfl_xor_sync(0xffffffffu, M, off));

    float L = 0.f;
    float4 o = make_float4(0.f, 0.f, 0.f, 0.f);
    #pragma unroll
    for (int k = 0; k < 8; k++) {
        int cn  = wj * 8 + k;
        int idx = (b * NCHUNK + cn) * HH + h;
        float al = __expf(__shfl_sync(0xffffffffu, mraw, cn) - M);
        L += al * g_l[idx];
        float4 a = ((const float4*)g_acc)[(((size_t)idx * DD) >> 2) + l];
        o.x += al * a.x; o.y += al * a.y; o.z += al * a.z; o.w += al * a.w;
    }
    osm[wj][l] = o;
    if (l == 0) Lsm[wj] = L;
    __syncthreads();

    if (wj == 0) {
        float4 t1 = osm[1][l], t2 = osm[2][l], t3 = osm[3][l];
        o.x += t1.x + t2.x + t3.x;
        o.y += t1.y + t2.y + t3.y;
        o.z += t1.z + t2.z + t3.z;
        o.w += t1.w + t2.w + t3.w;
        float inv = 1.0f / (Lsm[0] + Lsm[1] + Lsm[2] + Lsm[3]);
        o.x *= inv; o.y *= inv; o.z *= inv; o.w *= inv;
        ((float4*)out)[(size_t)bh * 32 + l] = o;
    }
}

extern "C" void kernel_launch(void* const* d_in, const int* in_sizes, int n_in,
                              void* d_out, int out_size) {
    const float* query   = (const float*)d_in[0];
    const float* k_cache = (const float*)d_in[1];
    const float* v_cache = (const float*)d_in[2];
    const int*   slots   = (const int*)d_in[3];
    const int*   pos     = (const int*)d_in[4];
    float*       out     = (float*)d_out;

    attn_partial<<<dim3(NCHUNK, BB), NT>>>(query, k_cache, v_cache, slots, pos);
    attn_combine<<<BB * HH, 128>>>(out);
}